// round 13
// baseline (speedup 1.0000x reference)
#include <cuda_runtime.h>
#include <cuda_bf16.h>
#include <cstdint>
#include <math.h>

// ============================================================================
// Problem constants
// ============================================================================
#define HIDDEN   1024
#define BATCH    4096
#define M_TOTAL  16384          // BATCH * 4 pair rows
#define GCOLS    1024
#define KQ       3072
#define KZ       2048
#define BM       128
#define BG       64             // g-columns per CTA
#define NKT      48             // KQ / 64
#define NKT_Z    32             // KZ / 64
#define NOKT     24             // 128-k macro iterations
#define STAGE_BYTES 40960       // A 16KB + Bd 8KB + Bql 8KB + Bzl 8KB
#define OFF_BIAS (4 * STAGE_BYTES)          // 163840
#define OFF_RED  (OFF_BIAS + 768)
#define SMEM_USE (OFF_RED + 128)
#define SMEM_REQ (SMEM_USE + 1024)          // slack for manual 1KB align
#define SL_BLOCKS 32

// ============================================================================
// Scratch (__device__ globals; no allocation allowed)
// ============================================================================
__device__ __align__(128) __nv_bfloat16 g_cond[(size_t)M_TOTAL * KQ]; // 100 MB
__device__ __align__(128) __nv_bfloat16 g_Wd [(size_t)GCOLS * KQ];    // 6 MB  [g][k]
__device__ __align__(128) __nv_bfloat16 g_Wzl[(size_t)GCOLS * KZ];    // 4 MB
__device__ __align__(128) __nv_bfloat16 g_Wql[(size_t)GCOLS * KQ];    // 6 MB
__device__ float g_kl_partial[2048];
__device__ float g_small_partial[SL_BLOCKS * 4];

// ============================================================================
// PTX helpers (baseline sm_100 ISA only: cp.async, ldmatrix, mma.sync)
// ============================================================================
__device__ __forceinline__ uint32_t smem_to_u32(const void* p) {
    uint32_t a;
    asm("{ .reg .u64 t; cvta.to.shared.u64 t, %1; cvt.u32.u64 %0, t; }" : "=r"(a) : "l"(p));
    return a;
}
__device__ __forceinline__ void cp16(uint32_t dst, const void* src) {
    asm volatile("cp.async.cg.shared.global [%0], [%1], 16;" :: "r"(dst), "l"(src) : "memory");
}
#define CP_COMMIT() asm volatile("cp.async.commit_group;" ::: "memory")

#define LDSM4(r, addr) \
    asm volatile("ldmatrix.sync.aligned.m8n8.x4.shared.b16 {%0,%1,%2,%3}, [%4];" \
        : "=r"((r)[0]), "=r"((r)[1]), "=r"((r)[2]), "=r"((r)[3]) : "r"(addr))

#define MMA16816(c, a, b0, b1) \
    asm volatile("mma.sync.aligned.m16n8k16.row.col.f32.bf16.bf16.f32 " \
        "{%0,%1,%2,%3}, {%4,%5,%6,%7}, {%8,%9}, {%0,%1,%2,%3};" \
        : "+f"((c)[0]), "+f"((c)[1]), "+f"((c)[2]), "+f"((c)[3]) \
        : "r"((a)[0]), "r"((a)[1]), "r"((a)[2]), "r"((a)[3]), \
          "r"(b0), "r"(b1))

// ============================================================================
// Prep 1: cond[16384][3072] bf16 = [events[i,s] | events[i,s+1] | contexts[i,s]]
// ============================================================================
__global__ __launch_bounds__(256) void build_cond_kernel(
    const float* __restrict__ events, const float* __restrict__ contexts) {
    const int r = blockIdx.x;                 // 0..16383
    const int i = r >> 2, s = r & 3;
    const float* e0 = events + ((size_t)i * 5 + s) * HIDDEN;
    const float* e1 = e0 + HIDDEN;
    const float* cx = contexts + ((size_t)i * 4 + s) * HIDDEN;
    __nv_bfloat162* dst = (__nv_bfloat162*)(g_cond + (size_t)r * KQ);
    for (int t = threadIdx.x; t < 768; t += 256) {     // 768 float4 = 3072 floats
        const float* src = (t < 256) ? e0 : (t < 512) ? e1 : cx;
        float4 v = *(const float4*)(src + (size_t)(t & 255) * 4);
        dst[t * 2 + 0] = __floats2bfloat162_rn(v.x, v.y);
        dst[t * 2 + 1] = __floats2bfloat162_rn(v.z, v.w);
    }
}

// ============================================================================
// Prep 2: transposed bf16 weights
//   g_Wd [g][k] = (k<2048 ? Wz[k][g] : 0) - Wqz[k][g]   (k<3072)
//   g_Wzl[g][k] = Wv[k][g]                              (k<2048)
//   g_Wql[g][k] = Wqv[k][g]                             (k<3072)
// ============================================================================
__global__ void transpose_w_kernel(
    const float* __restrict__ Wz, const float* __restrict__ Wqz,
    const float* __restrict__ Wv, const float* __restrict__ Wqv) {
    __shared__ float tile[32][33];
    const int which = blockIdx.z;            // 0=d, 1=zl, 2=ql
    const int k0 = blockIdx.x * 32, g0 = blockIdx.y * 32;
    if (which == 1 && k0 >= KZ) return;
    const int tx = threadIdx.x, ty = threadIdx.y;
    for (int i = ty; i < 32; i += 8) {
        const int k = k0 + i;
        float v;
        if (which == 0)
            v = ((k < KZ) ? Wz[(size_t)k * GCOLS + g0 + tx] : 0.f)
                - Wqz[(size_t)k * GCOLS + g0 + tx];
        else if (which == 1)
            v = Wv[(size_t)k * GCOLS + g0 + tx];
        else
            v = Wqv[(size_t)k * GCOLS + g0 + tx];
        tile[i][tx] = v;
    }
    __syncthreads();
    for (int i = ty; i < 32; i += 8) {
        const __nv_bfloat16 b = __float2bfloat16(tile[tx][i]);
        if (which == 0)      g_Wd [(size_t)(g0 + i) * KQ + k0 + tx] = b;
        else if (which == 1) g_Wzl[(size_t)(g0 + i) * KZ + k0 + tx] = b;
        else                 g_Wql[(size_t)(g0 + i) * KQ + k0 + tx] = b;
    }
}

// ============================================================================
// No-op kernel keeps gemm_kl_kernel at ncu capture slot 5
// ============================================================================
__global__ void dummy_kernel() {}

// ============================================================================
// Fused triple-GEMM + KL epilogue (mma.sync bf16).
// grid (16 g-blocks, 128 m-tiles), 256 threads = 8 warps (2M x 4N).
// K=128 per macro-iteration, one barrier each. SMSP-mate warps (0-3 vs 4-7)
// process the two resident stages in OPPOSITE order to anti-align their
// LDSM windows and keep the tensor pipe fed.
// ============================================================================
__global__ __launch_bounds__(256, 1) void gemm_kl_kernel(
    const float* __restrict__ bz, const float* __restrict__ bqz,
    const float* __restrict__ bv, const float* __restrict__ bqv) {
    extern __shared__ char dsm[];
    const uint32_t raw = smem_to_u32(dsm);
    const uint32_t sb = (raw + 1023u) & ~1023u;
    char* smc = dsm + (sb - raw);
    const int tid = threadIdx.x;
    const int lane = tid & 31;
    const int wid = tid >> 5;
    const int stag = (wid >> 2) & 1;       // SMSP-mate selector (wid%4 == SMSP)
    const int nb0 = blockIdx.x * BG;
    const int m0 = blockIdx.y * BM;

    float* sBD = (float*)(smc + OFF_BIAS);        // 64
    float* sBZL = sBD + 64;                       // 64
    float* sBQL = sBZL + 64;                      // 64
    if (tid < 64) {
        sBD[tid]  = bz[nb0 + tid] - bqz[nb0 + tid];
        sBZL[tid] = bv[nb0 + tid];
        sBQL[tid] = bqv[nb0 + tid];
    }

    // ---- per-lane ldmatrix address components (xor swizzle) ----
    const int wm = wid & 1;          // 2 warps along M (64 rows each)
    const int wn = wid >> 1;         // 4 warps along N (16 cols each)
    const uint32_t aswz = (uint32_t)(lane & 7) * 16u;
    const uint32_t acb = (uint32_t)(lane >> 4) * 16u;
    uint32_t aoff[4];
#pragma unroll
    for (int p = 0; p < 4; p++)
        aoff[p] = (uint32_t)(wm * 64 + p * 16 + (lane & 15)) * 128u;
    const int brr = (wn & 3) * 16 + ((lane >> 4) << 3) + (lane & 7);
    const uint32_t boff = (uint32_t)brr * 128u;
    const uint32_t bswz = (uint32_t)(lane & 7) * 16u;
    const uint32_t bcb = (uint32_t)((lane >> 3) & 1) * 16u;

    // ---- accumulators: [p=4 m-frags][h=2 n-halves][4] per matrix ----
    float accD[4][2][4], accZL[4][2][4], accQL[4][2][4];
#pragma unroll
    for (int p = 0; p < 4; p++)
#pragma unroll
        for (int h = 0; h < 2; h++)
#pragma unroll
            for (int c = 0; c < 4; c++) {
                accD[p][h][c] = 0.f; accZL[p][h][c] = 0.f; accQL[p][h][c] = 0.f;
            }

    // ---- precomputed loader addressing (static per thread across kt) ----
    uint32_t dstoff[10];
    const char* srcp[10];
#pragma unroll
    for (int it = 0; it < 10; it++) {
        const int c = tid + it * 256;
        const int cb = c & 7;
        if (c < 1024) {
            const int row = c >> 3;
            dstoff[it] = (uint32_t)(row * 128 + cb * 16) ^ ((uint32_t)(row & 7) * 16u);
            srcp[it] = (const char*)(g_cond + (size_t)(m0 + row) * KQ) + cb * 16;
        } else if (c < 1536) {
            const int row = (c - 1024) >> 3;
            dstoff[it] = 16384u + ((uint32_t)(row * 128 + cb * 16) ^ ((uint32_t)(row & 7) * 16u));
            srcp[it] = (const char*)(g_Wd + (size_t)(nb0 + row) * KQ) + cb * 16;
        } else if (c < 2048) {
            const int row = (c - 1536) >> 3;
            dstoff[it] = 24576u + ((uint32_t)(row * 128 + cb * 16) ^ ((uint32_t)(row & 7) * 16u));
            srcp[it] = (const char*)(g_Wql + (size_t)(nb0 + row) * KQ) + cb * 16;
        } else {
            const int row = (c - 2048) >> 3;
            dstoff[it] = 32768u + ((uint32_t)(row * 128 + cb * 16) ^ ((uint32_t)(row & 7) * 16u));
            srcp[it] = (const char*)(g_Wzl + (size_t)(nb0 + row) * KZ) + cb * 16;
        }
    }

#define LOAD_STAGE(kt) do { \
        const uint32_t _base = sb + (uint32_t)((kt) & 3) * STAGE_BYTES; \
        const int _kb = (kt) * 128; \
        _Pragma("unroll") \
        for (int _it = 0; _it < 8; _it++) cp16(_base + dstoff[_it], srcp[_it] + _kb); \
        if ((kt) < NKT_Z) { \
            cp16(_base + dstoff[8], srcp[8] + _kb); \
            cp16(_base + dstoff[9], srcp[9] + _kb); \
        } \
        CP_COMMIT(); \
    } while (0)

    // ---- fragment double buffers ----
    uint32_t aF[2][4][4], fdF[2][4], fqlF[2][4], fzlF[2][4];

#define LDFRAG(buf, ks, stA, full) do { \
        const uint32_t _ka = (((uint32_t)(ks) * 32u + acb) ^ aswz); \
        const uint32_t _kb = (((uint32_t)(ks) * 32u + bcb) ^ bswz); \
        LDSM4(aF[buf][0], (stA) + aoff[0] + _ka); \
        LDSM4(aF[buf][1], (stA) + aoff[1] + _ka); \
        LDSM4(aF[buf][2], (stA) + aoff[2] + _ka); \
        LDSM4(aF[buf][3], (stA) + aoff[3] + _ka); \
        LDSM4(fdF[buf],  (stA) + 16384u + boff + _kb); \
        LDSM4(fqlF[buf], (stA) + 24576u + boff + _kb); \
        if (full) LDSM4(fzlF[buf], (stA) + 32768u + boff + _kb); \
    } while (0)

#define DOMMA(buf, full) do { \
        _Pragma("unroll") \
        for (int _p = 0; _p < 4; _p++) { \
            _Pragma("unroll") \
            for (int _h = 0; _h < 2; _h++) { \
                MMA16816(accD[_p][_h],  aF[buf][_p], fdF[buf][2*_h],  fdF[buf][2*_h+1]); \
                MMA16816(accQL[_p][_h], aF[buf][_p], fqlF[buf][2*_h], fqlF[buf][2*_h+1]); \
            } \
        } \
        if (full) { \
            _Pragma("unroll") \
            for (int _p = 0; _p < 4; _p++) { \
                _Pragma("unroll") \
                for (int _h = 0; _h < 2; _h++) \
                    MMA16816(accZL[_p][_h], aF[buf][_p], fzlF[buf][2*_h], fzlF[buf][2*_h+1]); \
            } \
        } \
    } while (0)

    // ---- prologue: load first pair (kt 0,1); each warp-group prefetches
    //      ks0 of ITS first stage (group A: stage 0, group B: stage 1) ----
    LOAD_STAGE(0);
    LOAD_STAGE(1);
    asm volatile("cp.async.wait_group 0;" ::: "memory");
    __syncthreads();
    {
        const uint32_t stF0 = sb + (uint32_t)(stag ? STAGE_BYTES : 0);
        LDFRAG(0, 0, stF0, true);
    }

    for (int okt = 0; okt < NOKT; okt++) {
        const int kt0 = 2 * okt;
        const uint32_t st0 = sb + (uint32_t)(kt0 & 3) * STAGE_BYTES;
        const uint32_t st1 = sb + (uint32_t)((kt0 + 1) & 3) * STAGE_BYTES;
        // SMSP-mate stagger: group A walks (st0, st1); group B walks (st1, st0)
        const uint32_t stF = stag ? st1 : st0;
        const uint32_t stS = stag ? st0 : st1;
        const bool full = (kt0 < NKT_Z);     // pair shares fullness

        // buf0 already holds (stF, ks0) fragments
        LDFRAG(1, 1, stF, full);
        if (okt < NOKT - 1) {                // issue loads for next pair
            LOAD_STAGE(kt0 + 2);
            LOAD_STAGE(kt0 + 3);
        }
        DOMMA(0, full);                      // stF ks0
        LDFRAG(0, 2, stF, full); DOMMA(1, full);   // stF ks1
        LDFRAG(1, 3, stF, full); DOMMA(0, full);   // stF ks2
        LDFRAG(0, 0, stS, full); DOMMA(1, full);   // stF ks3
        LDFRAG(1, 1, stS, full); DOMMA(0, full);   // stS ks0
        LDFRAG(0, 2, stS, full); DOMMA(1, full);   // stS ks1
        LDFRAG(1, 3, stS, full); DOMMA(0, full);   // stS ks2
        if (okt < NOKT - 1) {
            asm volatile("cp.async.wait_group 0;" ::: "memory");
            __syncthreads();
            // next pair resident: group A prefetches kt0+2, group B kt0+3
            const uint32_t stN = sb +
                (uint32_t)((kt0 + 2 + stag) & 3) * STAGE_BYTES;
            const bool fulln = (kt0 + 2 < NKT_Z);
            LDFRAG(0, 0, stN, fulln);
        }
        DOMMA(1, full);                      // stS ks3
    }

    // ---- fused KL epilogue: identical fragment layouts -> no shuffles ----
    float acckl = 0.f;
#pragma unroll
    for (int p = 0; p < 4; p++) {
#pragma unroll
        for (int h = 0; h < 2; h++) {
            const int col = (wn & 3) * 16 + h * 8 + (lane & 3) * 2;
            const float bd0 = sBD[col], bd1 = sBD[col + 1];
            const float bl0 = sBZL[col], bl1 = sBZL[col + 1];
            const float bq0 = sBQL[col], bq1 = sBQL[col + 1];
#pragma unroll
            for (int r = 0; r < 2; r++) {
                const float d0 = accD[p][h][2 * r] + bd0;
                const float d1 = accD[p][h][2 * r + 1] + bd1;
                const float zl0 = accZL[p][h][2 * r] + bl0;
                const float zl1 = accZL[p][h][2 * r + 1] + bl1;
                const float ql0 = accQL[p][h][2 * r] + bq0;
                const float ql1 = accQL[p][h][2 * r + 1] + bq1;
                acckl += ql0 - zl0 + (expf(zl0) + d0 * d0) * expf(-ql0) - 1.f;
                acckl += ql1 - zl1 + (expf(zl1) + d1 * d1) * expf(-ql1) - 1.f;
            }
        }
    }

    // deterministic reduction over 8 warps
#pragma unroll
    for (int s = 16; s > 0; s >>= 1)
        acckl += __shfl_down_sync(0xFFFFFFFFu, acckl, s);
    float* red = (float*)(smc + OFF_RED);
    if (lane == 0) red[wid] = acckl;
    __syncthreads();
    if (tid == 0) {
        float s = 0.f;
        for (int w = 0; w < 8; w++) s += red[w];
        g_kl_partial[blockIdx.y * 16 + blockIdx.x] = s;
    }
}

// ============================================================================
// Small losses: 32 blocks x 128 threads, one batch element each
// ============================================================================
__global__ __launch_bounds__(128) void small_loss_kernel(
    const float* __restrict__ ps, const float* __restrict__ pt,
    const float* __restrict__ pc, const int* __restrict__ labels,
    const int* __restrict__ scene, const int* __restrict__ thr) {
    __shared__ float red[128];
    const int b = blockIdx.x * 128 + threadIdx.x;    // < 4096
    float wce = 0.f, wsum = 0.f, tsum = 0.f, vsum = 0.f;
    {
        const int lab = labels[b];
        const int s = scene[b], t = thr[b];
        const bool l5 = (lab == 5), l2 = (lab == 2), l3 = (lab == 3);
        const bool le = !(l5 | l2 | l3);
        const int nv = l5 ? 3 : (l2 ? 1 : (l3 ? 2 : 3));
        const int last = nv - 1;
        const float* psb = ps + (size_t)b * 6;
        const float* ptb = pt + (size_t)b * 6;
        const float* pcb = pc + (size_t)b * 6;
        #pragma unroll
        for (int slot = 0; slot < 3; slot++) {
            if (slot >= nv) break;
            int chain = l5 ? 1 : (l2 ? 0 : (l3 ? (slot == 0 ? 1 : 0)
                                               : (slot == 2 ? 0 : 1)));
            int ps_col = (!l5 && slot == last) ? s : 0;
            int pt_row = (l3 && slot == 1) ? (t == 1 ? 0 : 1) : slot;
            int pt_col = (l2 && slot == 0) ? t : ((le && slot == 2) ? t : 0);
            int pcs_col = l5 ? 1 : (slot == last ? 0 : 1);
            float PS = psb[slot * 2 + ps_col];
            float PT = ptb[pt_row * 2 + pt_col];
            float PCS = pcb[slot * 2 + pcs_col];
            float a0 = pcb[slot * 2 + 0], a1 = pcb[slot * 2 + 1];
            float mx = fmaxf(a0, a1);
            float lse = mx + logf(expf(a0 - mx) + expf(a1 - mx));
            float logp = (chain == 0 ? a0 : a1) - lse;
            float w = (chain == 0) ? 0.6f : 0.4f;
            wce += -w * logp;
            wsum += w;
            float lsig = fminf(PCS, 0.f) - log1pf(expf(-fabsf(PCS)));
            tsum += fabsf(logf(PS) + logf(PT) - lsig);
            vsum += 1.f;
        }
    }
    const int tid = threadIdx.x;
    float vals[4] = {wce, wsum, tsum, vsum};
    for (int v = 0; v < 4; v++) {
        red[tid] = vals[v];
        __syncthreads();
        for (int sft = 64; sft > 0; sft >>= 1) {
            if (tid < sft) red[tid] += red[tid + sft];
            __syncthreads();
        }
        if (tid == 0) g_small_partial[blockIdx.x * 4 + v] = red[0];
        __syncthreads();
    }
}

// ============================================================================
// Final combine
// ============================================================================
__global__ __launch_bounds__(1024) void combine_kernel(float* __restrict__ out) {
    __shared__ float red[1024];
    float s = 0.f;
    for (int i = threadIdx.x; i < 2048; i += 1024) s += g_kl_partial[i];
    red[threadIdx.x] = s;
    __syncthreads();
    for (int sft = 512; sft > 0; sft >>= 1) {
        if (threadIdx.x < sft) red[threadIdx.x] += red[threadIdx.x + sft];
        __syncthreads();
    }
    if (threadIdx.x == 0) {
        float sm[4] = {0.f, 0.f, 0.f, 0.f};
        for (int bi = 0; bi < SL_BLOCKS; bi++)
            for (int v = 0; v < 4; v++) sm[v] += g_small_partial[bi * 4 + v];
        const float kl_loss = 0.5f * red[0] / (float)M_TOTAL;
        out[0] = sm[0] / sm[1] + kl_loss + sm[2] / sm[3];
    }
}

// ============================================================================
// kernel_launch
// ============================================================================
extern "C" void kernel_launch(void* const* d_in, const int* in_sizes, int n_in,
                              void* d_out, int out_size) {
    const float* events   = (const float*)d_in[0];
    const float* contexts = (const float*)d_in[1];
    const float* ps       = (const float*)d_in[2];
    const float* pt       = (const float*)d_in[3];
    const float* pc       = (const float*)d_in[4];
    const int*   labels   = (const int*)d_in[5];
    const int*   scene    = (const int*)d_in[6];
    const int*   thr      = (const int*)d_in[7];
    const float* Wz  = (const float*)d_in[8];
    const float* bz  = (const float*)d_in[9];
    const float* Wv  = (const float*)d_in[10];
    const float* bv  = (const float*)d_in[11];
    const float* Wqz = (const float*)d_in[12];
    const float* bqz = (const float*)d_in[13];
    const float* Wqv = (const float*)d_in[14];
    const float* bqv = (const float*)d_in[15];
    float* out = (float*)d_out;

    cudaFuncSetAttribute(gemm_kl_kernel,
                         cudaFuncAttributeMaxDynamicSharedMemorySize, SMEM_REQ);

    build_cond_kernel<<<M_TOTAL, 256>>>(events, contexts);                       // my #0
    transpose_w_kernel<<<dim3(KQ / 32, GCOLS / 32, 3), dim3(32, 8)>>>(Wz, Wqz, Wv, Wqv); // #1
    dummy_kernel<<<1, 32>>>();                                                   // #2
    gemm_kl_kernel<<<dim3(GCOLS / BG, M_TOTAL / BM), 256, SMEM_REQ>>>(bz, bqz, bv, bqv); // #3 <- ncu slot 5
    small_loss_kernel<<<SL_BLOCKS, 128>>>(ps, pt, pc, labels, scene, thr);       // #4
    combine_kernel<<<1, 1024>>>(out);                                            // #5
}

// round 14
// speedup vs baseline: 1.0658x; 1.0658x over previous
#include <cuda_runtime.h>
#include <cuda_bf16.h>
#include <cstdint>
#include <math.h>

// ============================================================================
// Problem constants
// ============================================================================
#define HIDDEN   1024
#define BATCH    4096
#define M_TOTAL  16384          // BATCH * 4 pair rows
#define GCOLS    1024
#define KQ       3072
#define KZ       2048
#define BM       64             // rows per CTA
#define BG       64             // g-columns per CTA
#define NKT      48             // KQ / 64
#define NKT_Z    32             // KZ / 64
#define STAGE_BYTES 32768       // A 8KB + Bd 8KB + Bql 8KB + Bzl 8KB
#define OFF_BIAS (3 * STAGE_BYTES)          // 98304
#define OFF_RED  (OFF_BIAS + 768)
#define SMEM_USE (OFF_RED + 128)
#define SMEM_REQ (SMEM_USE + 1024)          // slack for manual 1KB align
#define SL_BLOCKS 32

// ============================================================================
// Scratch (__device__ globals; no allocation allowed)
// ============================================================================
__device__ __align__(128) __nv_bfloat16 g_cond[(size_t)M_TOTAL * KQ]; // 100 MB
__device__ __align__(128) __nv_bfloat16 g_Wd [(size_t)GCOLS * KQ];    // 6 MB  [g][k]
__device__ __align__(128) __nv_bfloat16 g_Wzl[(size_t)GCOLS * KZ];    // 4 MB
__device__ __align__(128) __nv_bfloat16 g_Wql[(size_t)GCOLS * KQ];    // 6 MB
__device__ float g_kl_partial[4096];
__device__ float g_small_partial[SL_BLOCKS * 4];

// ============================================================================
// PTX helpers (baseline sm_100 ISA only: cp.async, ldmatrix, mma.sync)
// ============================================================================
__device__ __forceinline__ uint32_t smem_to_u32(const void* p) {
    uint32_t a;
    asm("{ .reg .u64 t; cvta.to.shared.u64 t, %1; cvt.u32.u64 %0, t; }" : "=r"(a) : "l"(p));
    return a;
}
__device__ __forceinline__ void cp16(uint32_t dst, const void* src) {
    asm volatile("cp.async.cg.shared.global [%0], [%1], 16;" :: "r"(dst), "l"(src) : "memory");
}
#define CP_COMMIT() asm volatile("cp.async.commit_group;" ::: "memory")

#define LDSM4(r, addr) \
    asm volatile("ldmatrix.sync.aligned.m8n8.x4.shared.b16 {%0,%1,%2,%3}, [%4];" \
        : "=r"((r)[0]), "=r"((r)[1]), "=r"((r)[2]), "=r"((r)[3]) : "r"(addr))

#define MMA16816(c, a, b0, b1) \
    asm volatile("mma.sync.aligned.m16n8k16.row.col.f32.bf16.bf16.f32 " \
        "{%0,%1,%2,%3}, {%4,%5,%6,%7}, {%8,%9}, {%0,%1,%2,%3};" \
        : "+f"((c)[0]), "+f"((c)[1]), "+f"((c)[2]), "+f"((c)[3]) \
        : "r"((a)[0]), "r"((a)[1]), "r"((a)[2]), "r"((a)[3]), \
          "r"(b0), "r"(b1))

// ============================================================================
// Prep 1: cond[16384][3072] bf16 = [events[i,s] | events[i,s+1] | contexts[i,s]]
// ============================================================================
__global__ __launch_bounds__(256) void build_cond_kernel(
    const float* __restrict__ events, const float* __restrict__ contexts) {
    const int r = blockIdx.x;                 // 0..16383
    const int i = r >> 2, s = r & 3;
    const float* e0 = events + ((size_t)i * 5 + s) * HIDDEN;
    const float* e1 = e0 + HIDDEN;
    const float* cx = contexts + ((size_t)i * 4 + s) * HIDDEN;
    __nv_bfloat162* dst = (__nv_bfloat162*)(g_cond + (size_t)r * KQ);
    for (int t = threadIdx.x; t < 768; t += 256) {     // 768 float4 = 3072 floats
        const float* src = (t < 256) ? e0 : (t < 512) ? e1 : cx;
        float4 v = *(const float4*)(src + (size_t)(t & 255) * 4);
        dst[t * 2 + 0] = __floats2bfloat162_rn(v.x, v.y);
        dst[t * 2 + 1] = __floats2bfloat162_rn(v.z, v.w);
    }
}

// ============================================================================
// Prep 2: transposed bf16 weights
//   g_Wd [g][k] = (k<2048 ? Wz[k][g] : 0) - Wqz[k][g]   (k<3072)
//   g_Wzl[g][k] = Wv[k][g]                              (k<2048)
//   g_Wql[g][k] = Wqv[k][g]                             (k<3072)
// ============================================================================
__global__ void transpose_w_kernel(
    const float* __restrict__ Wz, const float* __restrict__ Wqz,
    const float* __restrict__ Wv, const float* __restrict__ Wqv) {
    __shared__ float tile[32][33];
    const int which = blockIdx.z;            // 0=d, 1=zl, 2=ql
    const int k0 = blockIdx.x * 32, g0 = blockIdx.y * 32;
    if (which == 1 && k0 >= KZ) return;
    const int tx = threadIdx.x, ty = threadIdx.y;
    for (int i = ty; i < 32; i += 8) {
        const int k = k0 + i;
        float v;
        if (which == 0)
            v = ((k < KZ) ? Wz[(size_t)k * GCOLS + g0 + tx] : 0.f)
                - Wqz[(size_t)k * GCOLS + g0 + tx];
        else if (which == 1)
            v = Wv[(size_t)k * GCOLS + g0 + tx];
        else
            v = Wqv[(size_t)k * GCOLS + g0 + tx];
        tile[i][tx] = v;
    }
    __syncthreads();
    for (int i = ty; i < 32; i += 8) {
        const __nv_bfloat16 b = __float2bfloat16(tile[tx][i]);
        if (which == 0)      g_Wd [(size_t)(g0 + i) * KQ + k0 + tx] = b;
        else if (which == 1) g_Wzl[(size_t)(g0 + i) * KZ + k0 + tx] = b;
        else                 g_Wql[(size_t)(g0 + i) * KQ + k0 + tx] = b;
    }
}

// ============================================================================
// No-op kernel keeps gemm_kl_kernel at ncu capture slot 5
// ============================================================================
__global__ void dummy_kernel() {}

// ============================================================================
// Fused triple-GEMM + KL epilogue (mma.sync bf16).
// grid (16 g-blocks, 256 m-tiles), 128 threads = 4 warps (1 per SMSP),
// 2 CTAs/SM with independent barriers -> natural anti-phase on each SMSP.
// Each warp: all 64 rows x its 16 cols x 3 matrices.
// 3-stage pipeline, distance-2 loads, cross-kt ks0 fragment prefetch.
// ============================================================================
__global__ __launch_bounds__(128, 2) void gemm_kl_kernel(
    const float* __restrict__ bz, const float* __restrict__ bqz,
    const float* __restrict__ bv, const float* __restrict__ bqv) {
    extern __shared__ char dsm[];
    const uint32_t raw = smem_to_u32(dsm);
    const uint32_t sb = (raw + 1023u) & ~1023u;
    char* smc = dsm + (sb - raw);
    const int tid = threadIdx.x;
    const int lane = tid & 31;
    const int wid = tid >> 5;              // 0..3 == SMSP
    const int nb0 = blockIdx.x * BG;
    const int m0 = blockIdx.y * BM;

    float* sBD = (float*)(smc + OFF_BIAS);        // 64
    float* sBZL = sBD + 64;                       // 64
    float* sBQL = sBZL + 64;                      // 64
    if (tid < 64) {
        sBD[tid]  = bz[nb0 + tid] - bqz[nb0 + tid];
        sBZL[tid] = bv[nb0 + tid];
        sBQL[tid] = bqv[nb0 + tid];
    }

    // ---- per-lane ldmatrix address components (xor swizzle) ----
    const int wn = wid;              // 4 warps along N (16 cols each)
    const uint32_t aswz = (uint32_t)(lane & 7) * 16u;
    const uint32_t acb = (uint32_t)(lane >> 4) * 16u;
    uint32_t aoff[4];
#pragma unroll
    for (int p = 0; p < 4; p++)
        aoff[p] = (uint32_t)(p * 16 + (lane & 15)) * 128u;
    const int brr = wn * 16 + ((lane >> 4) << 3) + (lane & 7);
    const uint32_t boff = (uint32_t)brr * 128u;
    const uint32_t bswz = (uint32_t)(lane & 7) * 16u;
    const uint32_t bcb = (uint32_t)((lane >> 3) & 1) * 16u;

    // ---- accumulators: [p=4 m-frags][h=2 n-halves][4] per matrix ----
    float accD[4][2][4], accZL[4][2][4], accQL[4][2][4];
#pragma unroll
    for (int p = 0; p < 4; p++)
#pragma unroll
        for (int h = 0; h < 2; h++)
#pragma unroll
            for (int c = 0; c < 4; c++) {
                accD[p][h][c] = 0.f; accZL[p][h][c] = 0.f; accQL[p][h][c] = 0.f;
            }

    // ---- precomputed loader addressing: 16 chunks/thread ----
    // c = tid + it*128: it0-3 A (512), it4-7 Bd, it8-11 Bql, it12-15 Bzl
    uint32_t dstoff[16];
    const char* srcp[16];
#pragma unroll
    for (int it = 0; it < 16; it++) {
        const int c = tid + it * 128;
        const int cb = c & 7;
        if (c < 512) {
            const int row = c >> 3;
            dstoff[it] = (uint32_t)(row * 128 + cb * 16) ^ ((uint32_t)(row & 7) * 16u);
            srcp[it] = (const char*)(g_cond + (size_t)(m0 + row) * KQ) + cb * 16;
        } else if (c < 1024) {
            const int row = (c - 512) >> 3;
            dstoff[it] = 8192u + ((uint32_t)(row * 128 + cb * 16) ^ ((uint32_t)(row & 7) * 16u));
            srcp[it] = (const char*)(g_Wd + (size_t)(nb0 + row) * KQ) + cb * 16;
        } else if (c < 1536) {
            const int row = (c - 1024) >> 3;
            dstoff[it] = 16384u + ((uint32_t)(row * 128 + cb * 16) ^ ((uint32_t)(row & 7) * 16u));
            srcp[it] = (const char*)(g_Wql + (size_t)(nb0 + row) * KQ) + cb * 16;
        } else {
            const int row = (c - 1536) >> 3;
            dstoff[it] = 24576u + ((uint32_t)(row * 128 + cb * 16) ^ ((uint32_t)(row & 7) * 16u));
            srcp[it] = (const char*)(g_Wzl + (size_t)(nb0 + row) * KZ) + cb * 16;
        }
    }

#define LOAD_STAGE(kt) do { \
        const uint32_t _base = sb + (uint32_t)((kt) % 3) * STAGE_BYTES; \
        const int _kb = (kt) * 128; \
        _Pragma("unroll") \
        for (int _it = 0; _it < 12; _it++) cp16(_base + dstoff[_it], srcp[_it] + _kb); \
        if ((kt) < NKT_Z) { \
            _Pragma("unroll") \
            for (int _it = 12; _it < 16; _it++) cp16(_base + dstoff[_it], srcp[_it] + _kb); \
        } \
        CP_COMMIT(); \
    } while (0)

    // ---- fragment double buffers ----
    uint32_t aF[2][4][4], fdF[2][4], fqlF[2][4], fzlF[2][4];

#define LDFRAG(buf, ks, stA, full) do { \
        const uint32_t _ka = (((uint32_t)(ks) * 32u + acb) ^ aswz); \
        const uint32_t _kb = (((uint32_t)(ks) * 32u + bcb) ^ bswz); \
        LDSM4(aF[buf][0], (stA) + aoff[0] + _ka); \
        LDSM4(aF[buf][1], (stA) + aoff[1] + _ka); \
        LDSM4(aF[buf][2], (stA) + aoff[2] + _ka); \
        LDSM4(aF[buf][3], (stA) + aoff[3] + _ka); \
        LDSM4(fdF[buf],  (stA) + 8192u + boff + _kb); \
        LDSM4(fqlF[buf], (stA) + 16384u + boff + _kb); \
        if (full) LDSM4(fzlF[buf], (stA) + 24576u + boff + _kb); \
    } while (0)

#define DOMMA(buf, full) do { \
        _Pragma("unroll") \
        for (int _p = 0; _p < 4; _p++) { \
            _Pragma("unroll") \
            for (int _h = 0; _h < 2; _h++) { \
                MMA16816(accD[_p][_h],  aF[buf][_p], fdF[buf][2*_h],  fdF[buf][2*_h+1]); \
                MMA16816(accQL[_p][_h], aF[buf][_p], fqlF[buf][2*_h], fqlF[buf][2*_h+1]); \
            } \
        } \
        if (full) { \
            _Pragma("unroll") \
            for (int _p = 0; _p < 4; _p++) { \
                _Pragma("unroll") \
                for (int _h = 0; _h < 2; _h++) \
                    MMA16816(accZL[_p][_h], aF[buf][_p], fzlF[buf][2*_h], fzlF[buf][2*_h+1]); \
            } \
        } \
    } while (0)

    // ---- prologue: 2 stages in flight, prefetch ks0 of stage 0 ----
    LOAD_STAGE(0);
    LOAD_STAGE(1);
    asm volatile("cp.async.wait_group 1;" ::: "memory");
    __syncthreads();
    LDFRAG(0, 0, sb, true);

    for (int kt = 0; kt < NKT; kt++) {
        const uint32_t stA = sb + (uint32_t)(kt % 3) * STAGE_BYTES;
        const bool full = (kt < NKT_Z);
        // buf0 already holds ks0 fragments (prefetched)
        LDFRAG(1, 1, stA, full);
        if (kt + 2 < NKT) LOAD_STAGE(kt + 2);
        DOMMA(0, full);
        LDFRAG(0, 2, stA, full);
        DOMMA(1, full);
        LDFRAG(1, 3, stA, full);
        DOMMA(0, full);
        if (kt < NKT - 1) {
            // stage kt+1 fully resident after this wait+barrier
            if (kt + 2 < NKT) { asm volatile("cp.async.wait_group 1;" ::: "memory"); }
            else              { asm volatile("cp.async.wait_group 0;" ::: "memory"); }
            __syncthreads();
            const uint32_t stN = sb + (uint32_t)((kt + 1) % 3) * STAGE_BYTES;
            const bool fulln = (kt + 1 < NKT_Z);
            LDFRAG(0, 0, stN, fulln);     // prefetch next kt's ks0
        }
        DOMMA(1, full);
    }

    // ---- fused KL epilogue: identical fragment layouts -> no shuffles ----
    float acckl = 0.f;
#pragma unroll
    for (int p = 0; p < 4; p++) {
#pragma unroll
        for (int h = 0; h < 2; h++) {
            const int col = wn * 16 + h * 8 + (lane & 3) * 2;
            const float bd0 = sBD[col], bd1 = sBD[col + 1];
            const float bl0 = sBZL[col], bl1 = sBZL[col + 1];
            const float bq0 = sBQL[col], bq1 = sBQL[col + 1];
#pragma unroll
            for (int r = 0; r < 2; r++) {
                const float d0 = accD[p][h][2 * r] + bd0;
                const float d1 = accD[p][h][2 * r + 1] + bd1;
                const float zl0 = accZL[p][h][2 * r] + bl0;
                const float zl1 = accZL[p][h][2 * r + 1] + bl1;
                const float ql0 = accQL[p][h][2 * r] + bq0;
                const float ql1 = accQL[p][h][2 * r + 1] + bq1;
                acckl += ql0 - zl0 + (expf(zl0) + d0 * d0) * expf(-ql0) - 1.f;
                acckl += ql1 - zl1 + (expf(zl1) + d1 * d1) * expf(-ql1) - 1.f;
            }
        }
    }

    // deterministic reduction over 4 warps
#pragma unroll
    for (int s = 16; s > 0; s >>= 1)
        acckl += __shfl_down_sync(0xFFFFFFFFu, acckl, s);
    float* red = (float*)(smc + OFF_RED);
    if (lane == 0) red[wid] = acckl;
    __syncthreads();
    if (tid == 0) {
        float s = 0.f;
        for (int w = 0; w < 4; w++) s += red[w];
        g_kl_partial[blockIdx.y * 16 + blockIdx.x] = s;
    }
}

// ============================================================================
// Small losses: 32 blocks x 128 threads, one batch element each
// ============================================================================
__global__ __launch_bounds__(128) void small_loss_kernel(
    const float* __restrict__ ps, const float* __restrict__ pt,
    const float* __restrict__ pc, const int* __restrict__ labels,
    const int* __restrict__ scene, const int* __restrict__ thr) {
    __shared__ float red[128];
    const int b = blockIdx.x * 128 + threadIdx.x;    // < 4096
    float wce = 0.f, wsum = 0.f, tsum = 0.f, vsum = 0.f;
    {
        const int lab = labels[b];
        const int s = scene[b], t = thr[b];
        const bool l5 = (lab == 5), l2 = (lab == 2), l3 = (lab == 3);
        const bool le = !(l5 | l2 | l3);
        const int nv = l5 ? 3 : (l2 ? 1 : (l3 ? 2 : 3));
        const int last = nv - 1;
        const float* psb = ps + (size_t)b * 6;
        const float* ptb = pt + (size_t)b * 6;
        const float* pcb = pc + (size_t)b * 6;
        #pragma unroll
        for (int slot = 0; slot < 3; slot++) {
            if (slot >= nv) break;
            int chain = l5 ? 1 : (l2 ? 0 : (l3 ? (slot == 0 ? 1 : 0)
                                               : (slot == 2 ? 0 : 1)));
            int ps_col = (!l5 && slot == last) ? s : 0;
            int pt_row = (l3 && slot == 1) ? (t == 1 ? 0 : 1) : slot;
            int pt_col = (l2 && slot == 0) ? t : ((le && slot == 2) ? t : 0);
            int pcs_col = l5 ? 1 : (slot == last ? 0 : 1);
            float PS = psb[slot * 2 + ps_col];
            float PT = ptb[pt_row * 2 + pt_col];
            float PCS = pcb[slot * 2 + pcs_col];
            float a0 = pcb[slot * 2 + 0], a1 = pcb[slot * 2 + 1];
            float mx = fmaxf(a0, a1);
            float lse = mx + logf(expf(a0 - mx) + expf(a1 - mx));
            float logp = (chain == 0 ? a0 : a1) - lse;
            float w = (chain == 0) ? 0.6f : 0.4f;
            wce += -w * logp;
            wsum += w;
            float lsig = fminf(PCS, 0.f) - log1pf(expf(-fabsf(PCS)));
            tsum += fabsf(logf(PS) + logf(PT) - lsig);
            vsum += 1.f;
        }
    }
    const int tid = threadIdx.x;
    float vals[4] = {wce, wsum, tsum, vsum};
    for (int v = 0; v < 4; v++) {
        red[tid] = vals[v];
        __syncthreads();
        for (int sft = 64; sft > 0; sft >>= 1) {
            if (tid < sft) red[tid] += red[tid + sft];
            __syncthreads();
        }
        if (tid == 0) g_small_partial[blockIdx.x * 4 + v] = red[0];
        __syncthreads();
    }
}

// ============================================================================
// Final combine
// ============================================================================
__global__ __launch_bounds__(1024) void combine_kernel(float* __restrict__ out) {
    __shared__ float red[1024];
    float s = 0.f;
    for (int i = threadIdx.x; i < 4096; i += 1024) s += g_kl_partial[i];
    red[threadIdx.x] = s;
    __syncthreads();
    for (int sft = 512; sft > 0; sft >>= 1) {
        if (threadIdx.x < sft) red[threadIdx.x] += red[threadIdx.x + sft];
        __syncthreads();
    }
    if (threadIdx.x == 0) {
        float sm[4] = {0.f, 0.f, 0.f, 0.f};
        for (int bi = 0; bi < SL_BLOCKS; bi++)
            for (int v = 0; v < 4; v++) sm[v] += g_small_partial[bi * 4 + v];
        const float kl_loss = 0.5f * red[0] / (float)M_TOTAL;
        out[0] = sm[0] / sm[1] + kl_loss + sm[2] / sm[3];
    }
}

// ============================================================================
// kernel_launch
// ============================================================================
extern "C" void kernel_launch(void* const* d_in, const int* in_sizes, int n_in,
                              void* d_out, int out_size) {
    const float* events   = (const float*)d_in[0];
    const float* contexts = (const float*)d_in[1];
    const float* ps       = (const float*)d_in[2];
    const float* pt       = (const float*)d_in[3];
    const float* pc       = (const float*)d_in[4];
    const int*   labels   = (const int*)d_in[5];
    const int*   scene    = (const int*)d_in[6];
    const int*   thr      = (const int*)d_in[7];
    const float* Wz  = (const float*)d_in[8];
    const float* bz  = (const float*)d_in[9];
    const float* Wv  = (const float*)d_in[10];
    const float* bv  = (const float*)d_in[11];
    const float* Wqz = (const float*)d_in[12];
    const float* bqz = (const float*)d_in[13];
    const float* Wqv = (const float*)d_in[14];
    const float* bqv = (const float*)d_in[15];
    float* out = (float*)d_out;

    cudaFuncSetAttribute(gemm_kl_kernel,
                         cudaFuncAttributeMaxDynamicSharedMemorySize, SMEM_REQ);

    build_cond_kernel<<<M_TOTAL, 256>>>(events, contexts);                       // my #0
    transpose_w_kernel<<<dim3(KQ / 32, GCOLS / 32, 3), dim3(32, 8)>>>(Wz, Wqz, Wv, Wqv); // #1
    dummy_kernel<<<1, 32>>>();                                                   // #2
    gemm_kl_kernel<<<dim3(GCOLS / BG, M_TOTAL / BM), 128, SMEM_REQ>>>(bz, bqz, bv, bqv); // #3 <- ncu slot 5
    small_loss_kernel<<<SL_BLOCKS, 128>>>(ps, pt, pc, labels, scene, thr);       // #4
    combine_kernel<<<1, 1024>>>(out);                                            // #5
}